// round 14
// baseline (speedup 1.0000x reference)
#include <cuda_runtime.h>
#include <cuda_fp16.h>
#include <cstdint>

#define BB 2048
#define TT 256
#define NVV 32
#define HH 64
#define GG 192
#define LL 32
#define OHH 64

__device__ float g_h[BB * HH];
__device__ float g_klrow[BB];
// xp planes: [t][bpair(1024)][g(192)] as half2 (pair = 2 batch rows). 201 MB.
__device__ __half2 g_xp2[(size_t)TT * 1024 * GG];

__device__ __forceinline__ float tanh_hw(float x) {
    float y;
    asm("tanh.approx.f32 %0, %1;" : "=f"(y) : "f"(x));
    return y;
}
__device__ __forceinline__ float sig_hw(float x) {
    return fmaf(tanh_hw(0.5f * x), 0.5f, 0.5f);
}

// =====================================================================
// xp GEMM via fp16 tensor cores, fp32 accumulate. (unchanged)
// =====================================================================
__global__ void __launch_bounds__(256) xp_kernel(
    const float* __restrict__ values, const float* __restrict__ maskp,
    const float* __restrict__ W_ih, const float* __restrict__ b_ih,
    const int* __restrict__ seqlen)
{
    __shared__ __half sW[192 * 72];
    __shared__ __half sX[128 * 72];

    const int tid = threadIdx.x;
    const int bbase = blockIdx.x * 128;
    const int sqmax = __ldg(seqlen + bbase);   // sorted desc -> max of block

    if (sqmax <= (int)(blockIdx.y * 4)) return;

    for (int i = tid; i < GG * HH; i += 256) {
        int g = i >> 6, f = i & 63;
        sW[g * 72 + f] = __float2half(W_ih[i]);
    }

    const int w = tid >> 5, l = tid & 31;
    const int wg = w >> 2;
    const int wb = w & 3;
    const int l4 = l >> 2;
    const int l2 = (l & 3) * 2;

    for (int tloc = 0; tloc < 4; tloc++) {
        const int t = blockIdx.y * 4 + tloc;
        if (t >= sqmax) break;
        const int tt = TT - 1 - t;

        if (tloc > 0) __syncthreads();
        for (int i = tid; i < 128 * HH; i += 256) {
            int bl = i >> 6, f = i & 63;
            size_t base = (size_t)(bbase + bl) * TT * NVV + (size_t)tt * NVV;
            float v = (f < NVV) ? values[base + f] : maskp[base + f - NVV];
            sX[bl * 72 + f] = __float2half(v);
        }
        __syncthreads();

        #pragma unroll
        for (int gt = 0; gt < 6; gt++) {
            const int g0 = wg * 96 + gt * 16;
            uint32_t a[4][4];
            #pragma unroll
            for (int kk = 0; kk < 4; kk++) {
                const __half* p = &sW[(g0 + l4) * 72 + kk * 16 + l2];
                a[kk][0] = *(const uint32_t*)(p);
                a[kk][1] = *(const uint32_t*)(p + 8 * 72);
                a[kk][2] = *(const uint32_t*)(p + 8);
                a[kk][3] = *(const uint32_t*)(p + 8 * 72 + 8);
            }
            const float bias0 = __ldg(b_ih + g0 + l4);
            const float bias1 = __ldg(b_ih + g0 + 8 + l4);

            #pragma unroll
            for (int bt = 0; bt < 4; bt++) {
                const int b0 = wb * 32 + bt * 8;
                float c0 = bias0, c1 = bias0, c2 = bias1, c3 = bias1;
                #pragma unroll
                for (int kk = 0; kk < 4; kk++) {
                    const __half* bp = &sX[(b0 + l4) * 72 + kk * 16 + l2];
                    uint32_t br0 = *(const uint32_t*)(bp);
                    uint32_t br1 = *(const uint32_t*)(bp + 8);
                    asm volatile(
                        "mma.sync.aligned.m16n8k16.row.col.f32.f16.f16.f32 "
                        "{%0,%1,%2,%3}, {%4,%5,%6,%7}, {%8,%9}, {%0,%1,%2,%3};\n"
                        : "+f"(c0), "+f"(c1), "+f"(c2), "+f"(c3)
                        : "r"(a[kk][0]), "r"(a[kk][1]), "r"(a[kk][2]), "r"(a[kk][3]),
                          "r"(br0), "r"(br1));
                }
                const int gg = g0 + l4;
                const int bpair = (bbase + b0 + l2) >> 1;
                size_t base = ((size_t)t * 1024 + bpair) * 192 + gg;
                g_xp2[base]     = __floats2half2_rn(c0, c1);
                g_xp2[base + 8] = __floats2half2_rn(c2, c3);
            }
        }
    }
}

// =====================================================================
// GRU scan: 2-term split-fp16 MMA, 256 CTAs x 128 thr, 8 rows/CTA.
// DEPENDENCY-CHAIN SPLIT: per gate, 4 independent partial accumulators
// (hi/kt01, hi/kt23, lo/kt01, lo/kt23) -> MMA chain depth 8 -> 2.
// Early exit at t = seqlen[row0]; complementary job pairing kept.
// =====================================================================
#define GRU_SMEM_B ((192*72*2 + 2*8*72) * 2)

__global__ void __launch_bounds__(128) gru_kernel(
    const int* __restrict__ seqlen,
    const float* __restrict__ W_hh, const float* __restrict__ b_hh)
{
    extern __shared__ char smem[];
    __half* sWhi = (__half*)smem;            // [192][72]
    __half* sWlo = sWhi + 192 * 72;          // [192][72]
    __half* sH   = sWlo + 192 * 72;          // [2buf][8][72]
#define SH(buf, n, k) sH[(((buf) * 8) + (n)) * 72 + (k)]

    const int tid  = threadIdx.x;
    const int bid  = blockIdx.x;
    const int job  = (bid < 148) ? bid : (403 - bid);
    const int row0 = job * 8;
    const int seqmax = __ldg(seqlen + row0);

    for (int i = tid; i < GG * HH; i += 128) {
        int g = i >> 6, k = i & 63;
        float wv = W_hh[i];
        __half hi = __float2half(wv);
        __half lo = __float2half(wv - __half2float(hi));
        sWhi[g * 72 + k] = hi;
        sWlo[g * 72 + k] = lo;
    }
    for (int i = tid; i < 2 * 8 * 72; i += 128) sH[i] = __float2half(0.f);
    __syncthreads();

    const int l  = tid & 31;
    const int mw = tid >> 5;       // 0..3: j-tile 16mw..+15
    const int r  = l >> 2;         // 0..7
    const int cq = (l & 3) * 2;    // 0,2,4,6

    uint32_t Ahi[3][4][4], Alo[3][4][4];
    #pragma unroll
    for (int mt = 0; mt < 3; mt++) {
        const int g0 = 16 * mw + 64 * mt;
        #pragma unroll
        for (int kt = 0; kt < 4; kt++) {
            const int k0 = kt * 16 + cq;
            Ahi[mt][kt][0] = *(const uint32_t*)&sWhi[(g0 + r) * 72 + k0];
            Ahi[mt][kt][1] = *(const uint32_t*)&sWhi[(g0 + r + 8) * 72 + k0];
            Ahi[mt][kt][2] = *(const uint32_t*)&sWhi[(g0 + r) * 72 + k0 + 8];
            Ahi[mt][kt][3] = *(const uint32_t*)&sWhi[(g0 + r + 8) * 72 + k0 + 8];
            Alo[mt][kt][0] = *(const uint32_t*)&sWlo[(g0 + r) * 72 + k0];
            Alo[mt][kt][1] = *(const uint32_t*)&sWlo[(g0 + r + 8) * 72 + k0];
            Alo[mt][kt][2] = *(const uint32_t*)&sWlo[(g0 + r) * 72 + k0 + 8];
            Alo[mt][kt][3] = *(const uint32_t*)&sWlo[(g0 + r + 8) * 72 + k0 + 8];
        }
    }

    const int j0 = 16 * mw + r;
    const int j1 = j0 + 8;
    const int nloc = cq;
    const int grow = row0 + nloc;
    const float bhr0 = __ldg(b_hh + j0),        bhr1 = __ldg(b_hh + j1);
    const float bhz0 = __ldg(b_hh + 64 + j0),   bhz1 = __ldg(b_hh + 64 + j1);
    const float bhn0 = __ldg(b_hh + 128 + j0),  bhn1 = __ldg(b_hh + 128 + j1);
    const int seq0 = __ldg(seqlen + grow);
    const int seq1 = __ldg(seqlen + grow + 1);

    float hp[4] = {0.f, 0.f, 0.f, 0.f};

    const size_t bp = (size_t)(grow >> 1);
    const __half2* __restrict__ xplane = g_xp2 + bp * 192;
#define XPLANE(T) (xplane + (size_t)(T) * 1024 * 192)

    __half2 cur0 = XPLANE(0)[j0],       cur1 = XPLANE(0)[j1];
    __half2 cur2 = XPLANE(0)[64 + j0],  cur3 = XPLANE(0)[64 + j1];
    __half2 cur4 = XPLANE(0)[128 + j0], cur5 = XPLANE(0)[128 + j1];
    __half2 nxt0 = XPLANE(1)[j0],       nxt1 = XPLANE(1)[j1];
    __half2 nxt2 = XPLANE(1)[64 + j0],  nxt3 = XPLANE(1)[64 + j1];
    __half2 nxt4 = XPLANE(1)[128 + j0], nxt5 = XPLANE(1)[128 + j1];

    for (int t = 0; t < seqmax; t++) {
        const int buf = t & 1;
        __half2 tm0, tm1, tm2, tm3, tm4, tm5;
        if (t + 2 < TT) {
            const __half2* pl = XPLANE(t + 2);
            tm0 = pl[j0];       tm1 = pl[j1];
            tm2 = pl[64 + j0];  tm3 = pl[64 + j1];
            tm4 = pl[128 + j0]; tm5 = pl[128 + j1];
        }

        uint32_t bhi[4][2];
        #pragma unroll
        for (int kt = 0; kt < 4; kt++) {
            const int k0 = kt * 16 + cq;
            bhi[kt][0] = *(const uint32_t*)&SH(buf, r, k0);
            bhi[kt][1] = *(const uint32_t*)&SH(buf, r, k0 + 8);
        }

        float2 fR0 = __half22float2(cur0), fR1 = __half22float2(cur1);
        float2 fZ0 = __half22float2(cur2), fZ1 = __half22float2(cur3);
        float2 fN0 = __half22float2(cur4), fN1 = __half22float2(cur5);
        // 4 independent partial accumulators per gate:
        // p[0]=hi/kt01 (seeded with bias+xp), p[1]=hi/kt23, p[2]=lo/kt01, p[3]=lo/kt23
        float p[3][4][4];
        #pragma unroll
        for (int mt = 0; mt < 3; mt++)
            #pragma unroll
            for (int q = 1; q < 4; q++)
                #pragma unroll
                for (int e = 0; e < 4; e++) p[mt][q][e] = 0.f;
        p[0][0][0] = fR0.x + bhr0; p[0][0][1] = fR0.y + bhr0;
        p[0][0][2] = fR1.x + bhr1; p[0][0][3] = fR1.y + bhr1;
        p[1][0][0] = fZ0.x + bhz0; p[1][0][1] = fZ0.y + bhz0;
        p[1][0][2] = fZ1.x + bhz1; p[1][0][3] = fZ1.y + bhz1;
        p[2][0][0] = bhn0; p[2][0][1] = bhn0;
        p[2][0][2] = bhn1; p[2][0][3] = bhn1;
        float fxn[4] = {fN0.x, fN0.y, fN1.x, fN1.y};

#define MMA_ACC(P, A, B0, B1)                                                \
        asm volatile(                                                        \
            "mma.sync.aligned.m16n8k16.row.col.f32.f16.f16.f32 "             \
            "{%0,%1,%2,%3}, {%4,%5,%6,%7}, {%8,%9}, {%0,%1,%2,%3};\n"        \
            : "+f"((P)[0]), "+f"((P)[1]), "+f"((P)[2]), "+f"((P)[3])         \
            : "r"((A)[0]), "r"((A)[1]), "r"((A)[2]), "r"((A)[3]),            \
              "r"(B0), "r"(B1));

        #pragma unroll
        for (int mt = 0; mt < 3; mt++) {
            MMA_ACC(p[mt][0], Ahi[mt][0], bhi[0][0], bhi[0][1])
            MMA_ACC(p[mt][1], Ahi[mt][2], bhi[2][0], bhi[2][1])
            MMA_ACC(p[mt][2], Alo[mt][0], bhi[0][0], bhi[0][1])
            MMA_ACC(p[mt][3], Alo[mt][2], bhi[2][0], bhi[2][1])
        }
        #pragma unroll
        for (int mt = 0; mt < 3; mt++) {
            MMA_ACC(p[mt][0], Ahi[mt][1], bhi[1][0], bhi[1][1])
            MMA_ACC(p[mt][1], Ahi[mt][3], bhi[3][0], bhi[3][1])
            MMA_ACC(p[mt][2], Alo[mt][1], bhi[1][0], bhi[1][1])
            MMA_ACC(p[mt][3], Alo[mt][3], bhi[3][0], bhi[3][1])
        }
#undef MMA_ACC

        float acc[3][4];
        #pragma unroll
        for (int mt = 0; mt < 3; mt++)
            #pragma unroll
            for (int e = 0; e < 4; e++)
                acc[mt][e] = (p[mt][0][e] + p[mt][1][e]) + (p[mt][2][e] + p[mt][3][e]);

        #pragma unroll
        for (int e = 0; e < 4; e++) {
            float rr = sig_hw(acc[0][e]);
            float zz = sig_hw(acc[1][e]);
            float nn = tanh_hw(fxn[e] + rr * acc[2][e]);
            float hn = (1.f - zz) * nn + zz * hp[e];
            int sq = (e & 1) ? seq1 : seq0;
            hp[e] = (t < sq) ? hn : hp[e];
        }

        const int b2 = buf ^ 1;
        #pragma unroll
        for (int e = 0; e < 4; e++) {
            const int nn_ = nloc + (e & 1);
            const int jj_ = (e < 2) ? j0 : j1;
            SH(b2, nn_, jj_) = __float2half(hp[e]);
        }

        cur0 = nxt0; cur1 = nxt1; cur2 = nxt2; cur3 = nxt3; cur4 = nxt4; cur5 = nxt5;
        nxt0 = tm0; nxt1 = tm1; nxt2 = tm2; nxt3 = tm3; nxt4 = tm4; nxt5 = tm5;
        __syncthreads();
    }

    g_h[(size_t)(grow)     * HH + j0] = hp[0];
    g_h[(size_t)(grow + 1) * HH + j0] = hp[1];
    g_h[(size_t)(grow)     * HH + j1] = hp[2];
    g_h[(size_t)(grow + 1) * HH + j1] = hp[3];
#undef SH
#undef XPLANE
}

// =====================================================================
// Fused tail: z0 -> RK4 ODE -> decoder -> KL partials. (unchanged)
// =====================================================================
#define NSTEP 8
#define R4 4

__global__ void __launch_bounds__(128) tail_kernel(
    const float* __restrict__ eps,
    const float* __restrict__ Wz0, const float* __restrict__ bz0,
    const float* __restrict__ W1, const float* __restrict__ b1,
    const float* __restrict__ W2, const float* __restrict__ b2,
    const float* __restrict__ W3, const float* __restrict__ b3,
    const float* __restrict__ dW1, const float* __restrict__ db1,
    const float* __restrict__ dW2, const float* __restrict__ db2,
    float* __restrict__ out)
{
    __shared__ float sW1[32 * 64];
    __shared__ float sW2[64 * 64];
    __shared__ float sW3[64 * 32];
    __shared__ float sb1[64], sb2[64], sb3[32];
    __shared__ float sH[R4 * 64];
    __shared__ float z0p[R4 * 64];
    __shared__ float zc[32 * R4], za[32 * R4], zin[32 * R4], kb[32 * R4];
    __shared__ float sh1[64 * R4], sh2[64 * R4];

    const int tid = threadIdx.x;
    const int row0 = blockIdx.x * R4;

    for (int i = tid; i < OHH * LL; i += 128) {
        int o = i >> 5, f = i & 31;
        sW1[f * 64 + o] = W1[i];
    }
    for (int i = tid; i < LL * OHH; i += 128) {
        int l = i >> 6, f2 = i & 63;
        sW3[f2 * 32 + l] = W3[i];
    }
    for (int i = tid; i < OHH * OHH; i += 128) {
        int o = i >> 6, f = i & 63;
        sW2[f * 64 + o] = W2[i];
    }
    if (tid < 64) { sb1[tid] = b1[tid]; sb2[tid] = b2[tid]; }
    if (tid < 32) sb3[tid] = b3[tid];
    for (int i = tid; i < R4 * 64; i += 128)
        sH[i] = g_h[(size_t)(row0 + (i >> 6)) * HH + (i & 63)];
    __syncthreads();

    {
        const int o = tid & 63, rp = tid >> 6;
        float m0 = __ldg(bz0 + o), m1 = m0;
        #pragma unroll 8
        for (int f = 0; f < HH; f++) {
            float wv = __ldg(Wz0 + o * HH + f);
            m0 = fmaf(wv, sH[rp * 64 + f], m0);
            m1 = fmaf(wv, sH[(rp + 2) * 64 + f], m1);
        }
        z0p[rp * 64 + o] = m0;
        z0p[(rp + 2) * 64 + o] = m1;
    }
    __syncthreads();

    {
        const int row = tid >> 5, l = tid & 31;
        float m  = z0p[row * 64 + l];
        float lv = z0p[row * 64 + 32 + l];
        float z = m + eps[(size_t)(row0 + row) * LL + l] * __expf(0.5f * lv);
        zc[l * R4 + row] = z;
        float kt = 1.f + lv - m * m - __expf(lv);
        #pragma unroll
        for (int off = 16; off; off >>= 1) kt += __shfl_down_sync(0xffffffffu, kt, off);
        if (l == 0) g_klrow[row0 + row] = kt;
    }
    __syncthreads();

    const float hs = 48.0f / NSTEP;
    const int o64 = tid & 63, rp = tid >> 6;
    const int o32 = tid & 31, rw = tid >> 5;

#define ODE_EVAL(SRC)                                                        \
    {                                                                        \
        float a0 = sb1[o64], a1 = a0;                                        \
        _Pragma("unroll 8")                                                  \
        for (int f = 0; f < LL; f++) {                                       \
            float wv = sW1[f * 64 + o64];                                    \
            float4 zv = *(const float4*)((SRC) + f * R4);                    \
            float u0 = rp ? zv.y : zv.x;                                     \
            float u1 = rp ? zv.w : zv.z;                                     \
            a0 = fmaf(wv, u0, a0); a1 = fmaf(wv, u1, a1);                    \
        }                                                                    \
        sh1[o64 * R4 + rp]     = tanh_hw(a0);                                \
        sh1[o64 * R4 + rp + 2] = tanh_hw(a1);                                \
    }                                                                        \
    __syncthreads();                                                         \
    {                                                                        \
        float a0 = sb2[o64], a1 = a0;                                        \
        _Pragma("unroll 8")                                                  \
        for (int f = 0; f < OHH; f++) {                                      \
            float wv = sW2[f * 64 + o64];                                    \
            float4 zv = *(const float4*)(sh1 + f * R4);                      \
            float u0 = rp ? zv.y : zv.x;                                     \
            float u1 = rp ? zv.w : zv.z;                                     \
            a0 = fmaf(wv, u0, a0); a1 = fmaf(wv, u1, a1);                    \
        }                                                                    \
        sh2[o64 * R4 + rp]     = tanh_hw(a0);                                \
        sh2[o64 * R4 + rp + 2] = tanh_hw(a1);                                \
    }                                                                        \
    __syncthreads();                                                         \
    {                                                                        \
        float a = sb3[o32];                                                  \
        _Pragma("unroll 8")                                                  \
        for (int f = 0; f < OHH; f++)                                        \
            a = fmaf(sW3[f * 32 + o32], sh2[f * R4 + rw], a);                \
        kb[o32 * R4 + rw] = a;                                               \
    }                                                                        \
    __syncthreads();

    for (int s = 0; s < NSTEP; s++) {
        ODE_EVAL(zc)
        za[tid]  = fmaf(hs / 6.f, kb[tid], zc[tid]);
        zin[tid] = fmaf(hs * 0.5f, kb[tid], zc[tid]);
        __syncthreads();
        ODE_EVAL(zin)
        za[tid]  = fmaf(hs / 3.f, kb[tid], za[tid]);
        zin[tid] = fmaf(hs * 0.5f, kb[tid], zc[tid]);
        __syncthreads();
        ODE_EVAL(zin)
        za[tid]  = fmaf(hs / 3.f, kb[tid], za[tid]);
        zin[tid] = fmaf(hs, kb[tid], zc[tid]);
        __syncthreads();
        ODE_EVAL(zin)
        zc[tid] = fmaf(hs / 6.f, kb[tid], za[tid]);
        __syncthreads();
    }
#undef ODE_EVAL

    {
        float a0 = __ldg(db1 + o64), a1 = a0;
        #pragma unroll 8
        for (int f = 0; f < LL; f++) {
            float wv = __ldg(dW1 + o64 * LL + f);
            float4 zv = *(const float4*)(zc + f * R4);
            float u0 = rp ? zv.y : zv.x;
            float u1 = rp ? zv.w : zv.z;
            a0 = fmaf(wv, u0, a0); a1 = fmaf(wv, u1, a1);
        }
        float w2 = __ldg(dW2 + o64);
        sh1[o64 * R4 + rp]     = fmaxf(a0, 0.f) * w2;
        sh1[o64 * R4 + rp + 2] = fmaxf(a1, 0.f) * w2;
    }
    __syncthreads();
    {
        const int row = tid >> 5, l = tid & 31;
        float s = sh1[l * R4 + row] + sh1[(l + 32) * R4 + row];
        #pragma unroll
        for (int off = 16; off; off >>= 1) s += __shfl_down_sync(0xffffffffu, s, off);
        if (l == 0) out[row0 + row] = s + __ldg(db2);
    }
}

__global__ void __launch_bounds__(1024) kl_kernel(float* __restrict__ out)
{
    __shared__ float s[1024];
    const int t = threadIdx.x;
    s[t] = g_klrow[t] + g_klrow[t + 1024];
    __syncthreads();
    for (int o = 512; o; o >>= 1) {
        if (t < o) s[t] += s[t + o];
        __syncthreads();
    }
    if (t == 0) out[BB] = -0.5f * s[0] / ((float)BB * (float)LL);
}

// =====================================================================
extern "C" void kernel_launch(void* const* d_in, const int* in_sizes, int n_in,
                              void* d_out, int out_size)
{
    const float* values = (const float*)d_in[1];
    const float* maskp  = (const float*)d_in[2];
    const int*   seql   = (const int*)d_in[3];
    const float* eps    = (const float*)d_in[4];
    const float* W_ih   = (const float*)d_in[5];
    const float* W_hh   = (const float*)d_in[6];
    const float* b_ih   = (const float*)d_in[7];
    const float* b_hh   = (const float*)d_in[8];
    const float* W_z0   = (const float*)d_in[9];
    const float* b_z0   = (const float*)d_in[10];
    const float* oW1    = (const float*)d_in[11];
    const float* ob1    = (const float*)d_in[12];
    const float* oW2    = (const float*)d_in[13];
    const float* ob2    = (const float*)d_in[14];
    const float* oW3    = (const float*)d_in[15];
    const float* ob3    = (const float*)d_in[16];
    const float* dW1    = (const float*)d_in[17];
    const float* db1    = (const float*)d_in[18];
    const float* dW2    = (const float*)d_in[19];
    const float* db2    = (const float*)d_in[20];
    float* out = (float*)d_out;

    cudaFuncSetAttribute(gru_kernel, cudaFuncAttributeMaxDynamicSharedMemorySize, GRU_SMEM_B);

    xp_kernel<<<dim3(16, 64), 256>>>(values, maskp, W_ih, b_ih, seql);
    gru_kernel<<<256, 128, GRU_SMEM_B>>>(seql, W_hh, b_hh);
    tail_kernel<<<512, 128>>>(eps, W_z0, b_z0, oW1, ob1, oW2, ob2, oW3, ob3,
                              dW1, db1, dW2, db2, out);
    kl_kernel<<<1, 1024>>>(out);
}

// round 15
// speedup vs baseline: 1.1646x; 1.1646x over previous
#include <cuda_runtime.h>
#include <cuda_fp16.h>
#include <cstdint>

#define BB 2048
#define TT 256
#define NVV 32
#define HH 64
#define GG 192
#define LL 32
#define OHH 64

__device__ float g_h[BB * HH];
__device__ float g_klrow[BB];
// xp planes: [t][bpair(1024)][g(192)] as half2 (pair = 2 batch rows). 201 MB.
__device__ __half2 g_xp2[(size_t)TT * 1024 * GG];

__device__ __forceinline__ float tanh_hw(float x) {
    float y;
    asm("tanh.approx.f32 %0, %1;" : "=f"(y) : "f"(x));
    return y;
}
__device__ __forceinline__ float sig_hw(float x) {
    return fmaf(tanh_hw(0.5f * x), 0.5f, 0.5f);
}

// =====================================================================
// xp GEMM via fp16 tensor cores, fp32 accumulate. (unchanged)
// =====================================================================
__global__ void __launch_bounds__(256) xp_kernel(
    const float* __restrict__ values, const float* __restrict__ maskp,
    const float* __restrict__ W_ih, const float* __restrict__ b_ih,
    const int* __restrict__ seqlen)
{
    __shared__ __half sW[192 * 72];
    __shared__ __half sX[128 * 72];

    const int tid = threadIdx.x;
    const int bbase = blockIdx.x * 128;
    const int sqmax = __ldg(seqlen + bbase);   // sorted desc -> max of block

    if (sqmax <= (int)(blockIdx.y * 4)) return;

    for (int i = tid; i < GG * HH; i += 256) {
        int g = i >> 6, f = i & 63;
        sW[g * 72 + f] = __float2half(W_ih[i]);
    }

    const int w = tid >> 5, l = tid & 31;
    const int wg = w >> 2;
    const int wb = w & 3;
    const int l4 = l >> 2;
    const int l2 = (l & 3) * 2;

    for (int tloc = 0; tloc < 4; tloc++) {
        const int t = blockIdx.y * 4 + tloc;
        if (t >= sqmax) break;
        const int tt = TT - 1 - t;

        if (tloc > 0) __syncthreads();
        for (int i = tid; i < 128 * HH; i += 256) {
            int bl = i >> 6, f = i & 63;
            size_t base = (size_t)(bbase + bl) * TT * NVV + (size_t)tt * NVV;
            float v = (f < NVV) ? values[base + f] : maskp[base + f - NVV];
            sX[bl * 72 + f] = __float2half(v);
        }
        __syncthreads();

        #pragma unroll
        for (int gt = 0; gt < 6; gt++) {
            const int g0 = wg * 96 + gt * 16;
            uint32_t a[4][4];
            #pragma unroll
            for (int kk = 0; kk < 4; kk++) {
                const __half* p = &sW[(g0 + l4) * 72 + kk * 16 + l2];
                a[kk][0] = *(const uint32_t*)(p);
                a[kk][1] = *(const uint32_t*)(p + 8 * 72);
                a[kk][2] = *(const uint32_t*)(p + 8);
                a[kk][3] = *(const uint32_t*)(p + 8 * 72 + 8);
            }
            const float bias0 = __ldg(b_ih + g0 + l4);
            const float bias1 = __ldg(b_ih + g0 + 8 + l4);

            #pragma unroll
            for (int bt = 0; bt < 4; bt++) {
                const int b0 = wb * 32 + bt * 8;
                float c0 = bias0, c1 = bias0, c2 = bias1, c3 = bias1;
                #pragma unroll
                for (int kk = 0; kk < 4; kk++) {
                    const __half* bp = &sX[(b0 + l4) * 72 + kk * 16 + l2];
                    uint32_t br0 = *(const uint32_t*)(bp);
                    uint32_t br1 = *(const uint32_t*)(bp + 8);
                    asm volatile(
                        "mma.sync.aligned.m16n8k16.row.col.f32.f16.f16.f32 "
                        "{%0,%1,%2,%3}, {%4,%5,%6,%7}, {%8,%9}, {%0,%1,%2,%3};\n"
                        : "+f"(c0), "+f"(c1), "+f"(c2), "+f"(c3)
                        : "r"(a[kk][0]), "r"(a[kk][1]), "r"(a[kk][2]), "r"(a[kk][3]),
                          "r"(br0), "r"(br1));
                }
                const int gg = g0 + l4;
                const int bpair = (bbase + b0 + l2) >> 1;
                size_t base = ((size_t)t * 1024 + bpair) * 192 + gg;
                g_xp2[base]     = __floats2half2_rn(c0, c1);
                g_xp2[base + 8] = __floats2half2_rn(c2, c3);
            }
        }
    }
}

// =====================================================================
// GRU scan: PURE-fp16-W MMA (fp32 accumulate), 12 MMA/warp/step.
// 256 CTAs x 128 thr, 8 rows/CTA; early exit + complementary pairing.
// 2 independent partial accumulators per gate (depth-2 chains).
// =====================================================================
#define GRU_SMEM_B ((192*72 + 2*8*72) * 2)

__global__ void __launch_bounds__(128) gru_kernel(
    const int* __restrict__ seqlen,
    const float* __restrict__ W_hh, const float* __restrict__ b_hh)
{
    extern __shared__ char smem[];
    __half* sWhi = (__half*)smem;            // [192][72]
    __half* sH   = sWhi + 192 * 72;          // [2buf][8][72]
#define SH(buf, n, k) sH[(((buf) * 8) + (n)) * 72 + (k)]

    const int tid  = threadIdx.x;
    const int bid  = blockIdx.x;
    const int job  = (bid < 148) ? bid : (403 - bid);
    const int row0 = job * 8;
    const int seqmax = __ldg(seqlen + row0);

    for (int i = tid; i < GG * HH; i += 128) {
        int g = i >> 6, k = i & 63;
        sWhi[g * 72 + k] = __float2half(W_hh[i]);
    }
    for (int i = tid; i < 2 * 8 * 72; i += 128) sH[i] = __float2half(0.f);
    __syncthreads();

    const int l  = tid & 31;
    const int mw = tid >> 5;       // 0..3: j-tile 16mw..+15
    const int r  = l >> 2;         // 0..7
    const int cq = (l & 3) * 2;    // 0,2,4,6

    uint32_t Ahi[3][4][4];
    #pragma unroll
    for (int mt = 0; mt < 3; mt++) {
        const int g0 = 16 * mw + 64 * mt;
        #pragma unroll
        for (int kt = 0; kt < 4; kt++) {
            const int k0 = kt * 16 + cq;
            Ahi[mt][kt][0] = *(const uint32_t*)&sWhi[(g0 + r) * 72 + k0];
            Ahi[mt][kt][1] = *(const uint32_t*)&sWhi[(g0 + r + 8) * 72 + k0];
            Ahi[mt][kt][2] = *(const uint32_t*)&sWhi[(g0 + r) * 72 + k0 + 8];
            Ahi[mt][kt][3] = *(const uint32_t*)&sWhi[(g0 + r + 8) * 72 + k0 + 8];
        }
    }

    const int j0 = 16 * mw + r;
    const int j1 = j0 + 8;
    const int nloc = cq;
    const int grow = row0 + nloc;
    const float bhr0 = __ldg(b_hh + j0),        bhr1 = __ldg(b_hh + j1);
    const float bhz0 = __ldg(b_hh + 64 + j0),   bhz1 = __ldg(b_hh + 64 + j1);
    const float bhn0 = __ldg(b_hh + 128 + j0),  bhn1 = __ldg(b_hh + 128 + j1);
    const int seq0 = __ldg(seqlen + grow);
    const int seq1 = __ldg(seqlen + grow + 1);

    float hp[4] = {0.f, 0.f, 0.f, 0.f};

    const size_t bp = (size_t)(grow >> 1);
    const __half2* __restrict__ xplane = g_xp2 + bp * 192;
#define XPLANE(T) (xplane + (size_t)(T) * 1024 * 192)

    __half2 cur0 = XPLANE(0)[j0],       cur1 = XPLANE(0)[j1];
    __half2 cur2 = XPLANE(0)[64 + j0],  cur3 = XPLANE(0)[64 + j1];
    __half2 cur4 = XPLANE(0)[128 + j0], cur5 = XPLANE(0)[128 + j1];
    __half2 nxt0 = XPLANE(1)[j0],       nxt1 = XPLANE(1)[j1];
    __half2 nxt2 = XPLANE(1)[64 + j0],  nxt3 = XPLANE(1)[64 + j1];
    __half2 nxt4 = XPLANE(1)[128 + j0], nxt5 = XPLANE(1)[128 + j1];

    for (int t = 0; t < seqmax; t++) {
        const int buf = t & 1;
        __half2 tm0, tm1, tm2, tm3, tm4, tm5;
        if (t + 2 < TT) {
            const __half2* pl = XPLANE(t + 2);
            tm0 = pl[j0];       tm1 = pl[j1];
            tm2 = pl[64 + j0];  tm3 = pl[64 + j1];
            tm4 = pl[128 + j0]; tm5 = pl[128 + j1];
        }

        uint32_t bhi[4][2];
        #pragma unroll
        for (int kt = 0; kt < 4; kt++) {
            const int k0 = kt * 16 + cq;
            bhi[kt][0] = *(const uint32_t*)&SH(buf, r, k0);
            bhi[kt][1] = *(const uint32_t*)&SH(buf, r, k0 + 8);
        }

        float2 fR0 = __half22float2(cur0), fR1 = __half22float2(cur1);
        float2 fZ0 = __half22float2(cur2), fZ1 = __half22float2(cur3);
        float2 fN0 = __half22float2(cur4), fN1 = __half22float2(cur5);
        // 2 independent partial accumulators per gate (kt01, kt23)
        float p[3][2][4];
        #pragma unroll
        for (int mt = 0; mt < 3; mt++)
            #pragma unroll
            for (int e = 0; e < 4; e++) p[mt][1][e] = 0.f;
        p[0][0][0] = fR0.x + bhr0; p[0][0][1] = fR0.y + bhr0;
        p[0][0][2] = fR1.x + bhr1; p[0][0][3] = fR1.y + bhr1;
        p[1][0][0] = fZ0.x + bhz0; p[1][0][1] = fZ0.y + bhz0;
        p[1][0][2] = fZ1.x + bhz1; p[1][0][3] = fZ1.y + bhz1;
        p[2][0][0] = bhn0; p[2][0][1] = bhn0;
        p[2][0][2] = bhn1; p[2][0][3] = bhn1;
        float fxn[4] = {fN0.x, fN0.y, fN1.x, fN1.y};

#define MMA_ACC(P, A, B0, B1)                                                \
        asm volatile(                                                        \
            "mma.sync.aligned.m16n8k16.row.col.f32.f16.f16.f32 "             \
            "{%0,%1,%2,%3}, {%4,%5,%6,%7}, {%8,%9}, {%0,%1,%2,%3};\n"        \
            : "+f"((P)[0]), "+f"((P)[1]), "+f"((P)[2]), "+f"((P)[3])         \
            : "r"((A)[0]), "r"((A)[1]), "r"((A)[2]), "r"((A)[3]),            \
              "r"(B0), "r"(B1));

        #pragma unroll
        for (int mt = 0; mt < 3; mt++) {
            MMA_ACC(p[mt][0], Ahi[mt][0], bhi[0][0], bhi[0][1])
            MMA_ACC(p[mt][1], Ahi[mt][2], bhi[2][0], bhi[2][1])
        }
        #pragma unroll
        for (int mt = 0; mt < 3; mt++) {
            MMA_ACC(p[mt][0], Ahi[mt][1], bhi[1][0], bhi[1][1])
            MMA_ACC(p[mt][1], Ahi[mt][3], bhi[3][0], bhi[3][1])
        }
#undef MMA_ACC

        #pragma unroll
        for (int e = 0; e < 4; e++) {
            float rr = sig_hw(p[0][0][e] + p[0][1][e]);
            float zz = sig_hw(p[1][0][e] + p[1][1][e]);
            float nn = tanh_hw(fxn[e] + rr * (p[2][0][e] + p[2][1][e]));
            float hn = (1.f - zz) * nn + zz * hp[e];
            int sq = (e & 1) ? seq1 : seq0;
            hp[e] = (t < sq) ? hn : hp[e];
        }

        const int b2 = buf ^ 1;
        #pragma unroll
        for (int e = 0; e < 4; e++) {
            const int nn_ = nloc + (e & 1);
            const int jj_ = (e < 2) ? j0 : j1;
            SH(b2, nn_, jj_) = __float2half(hp[e]);
        }

        cur0 = nxt0; cur1 = nxt1; cur2 = nxt2; cur3 = nxt3; cur4 = nxt4; cur5 = nxt5;
        nxt0 = tm0; nxt1 = tm1; nxt2 = tm2; nxt3 = tm3; nxt4 = tm4; nxt5 = tm5;
        __syncthreads();
    }

    g_h[(size_t)(grow)     * HH + j0] = hp[0];
    g_h[(size_t)(grow + 1) * HH + j0] = hp[1];
    g_h[(size_t)(grow)     * HH + j1] = hp[2];
    g_h[(size_t)(grow + 1) * HH + j1] = hp[3];
#undef SH
#undef XPLANE
}

// =====================================================================
// Fused tail: z0 -> RK4 ODE (NSTEP=4) -> decoder -> KL partials.
// =====================================================================
#define NSTEP 4
#define R4 4

__global__ void __launch_bounds__(128) tail_kernel(
    const float* __restrict__ eps,
    const float* __restrict__ Wz0, const float* __restrict__ bz0,
    const float* __restrict__ W1, const float* __restrict__ b1,
    const float* __restrict__ W2, const float* __restrict__ b2,
    const float* __restrict__ W3, const float* __restrict__ b3,
    const float* __restrict__ dW1, const float* __restrict__ db1,
    const float* __restrict__ dW2, const float* __restrict__ db2,
    float* __restrict__ out)
{
    __shared__ float sW1[32 * 64];
    __shared__ float sW2[64 * 64];
    __shared__ float sW3[64 * 32];
    __shared__ float sb1[64], sb2[64], sb3[32];
    __shared__ float sH[R4 * 64];
    __shared__ float z0p[R4 * 64];
    __shared__ float zc[32 * R4], za[32 * R4], zin[32 * R4], kb[32 * R4];
    __shared__ float sh1[64 * R4], sh2[64 * R4];

    const int tid = threadIdx.x;
    const int row0 = blockIdx.x * R4;

    for (int i = tid; i < OHH * LL; i += 128) {
        int o = i >> 5, f = i & 31;
        sW1[f * 64 + o] = W1[i];
    }
    for (int i = tid; i < LL * OHH; i += 128) {
        int l = i >> 6, f2 = i & 63;
        sW3[f2 * 32 + l] = W3[i];
    }
    for (int i = tid; i < OHH * OHH; i += 128) {
        int o = i >> 6, f = i & 63;
        sW2[f * 64 + o] = W2[i];
    }
    if (tid < 64) { sb1[tid] = b1[tid]; sb2[tid] = b2[tid]; }
    if (tid < 32) sb3[tid] = b3[tid];
    for (int i = tid; i < R4 * 64; i += 128)
        sH[i] = g_h[(size_t)(row0 + (i >> 6)) * HH + (i & 63)];
    __syncthreads();

    {
        const int o = tid & 63, rp = tid >> 6;
        float m0 = __ldg(bz0 + o), m1 = m0;
        #pragma unroll 8
        for (int f = 0; f < HH; f++) {
            float wv = __ldg(Wz0 + o * HH + f);
            m0 = fmaf(wv, sH[rp * 64 + f], m0);
            m1 = fmaf(wv, sH[(rp + 2) * 64 + f], m1);
        }
        z0p[rp * 64 + o] = m0;
        z0p[(rp + 2) * 64 + o] = m1;
    }
    __syncthreads();

    {
        const int row = tid >> 5, l = tid & 31;
        float m  = z0p[row * 64 + l];
        float lv = z0p[row * 64 + 32 + l];
        float z = m + eps[(size_t)(row0 + row) * LL + l] * __expf(0.5f * lv);
        zc[l * R4 + row] = z;
        float kt = 1.f + lv - m * m - __expf(lv);
        #pragma unroll
        for (int off = 16; off; off >>= 1) kt += __shfl_down_sync(0xffffffffu, kt, off);
        if (l == 0) g_klrow[row0 + row] = kt;
    }
    __syncthreads();

    const float hs = 48.0f / NSTEP;
    const int o64 = tid & 63, rp = tid >> 6;
    const int o32 = tid & 31, rw = tid >> 5;

#define ODE_EVAL(SRC)                                                        \
    {                                                                        \
        float a0 = sb1[o64], a1 = a0;                                        \
        _Pragma("unroll 8")                                                  \
        for (int f = 0; f < LL; f++) {                                       \
            float wv = sW1[f * 64 + o64];                                    \
            float4 zv = *(const float4*)((SRC) + f * R4);                    \
            float u0 = rp ? zv.y : zv.x;                                     \
            float u1 = rp ? zv.w : zv.z;                                     \
            a0 = fmaf(wv, u0, a0); a1 = fmaf(wv, u1, a1);                    \
        }                                                                    \
        sh1[o64 * R4 + rp]     = tanh_hw(a0);                                \
        sh1[o64 * R4 + rp + 2] = tanh_hw(a1);                                \
    }                                                                        \
    __syncthreads();                                                         \
    {                                                                        \
        float a0 = sb2[o64], a1 = a0;                                        \
        _Pragma("unroll 8")                                                  \
        for (int f = 0; f < OHH; f++) {                                      \
            float wv = sW2[f * 64 + o64];                                    \
            float4 zv = *(const float4*)(sh1 + f * R4);                      \
            float u0 = rp ? zv.y : zv.x;                                     \
            float u1 = rp ? zv.w : zv.z;                                     \
            a0 = fmaf(wv, u0, a0); a1 = fmaf(wv, u1, a1);                    \
        }                                                                    \
        sh2[o64 * R4 + rp]     = tanh_hw(a0);                                \
        sh2[o64 * R4 + rp + 2] = tanh_hw(a1);                                \
    }                                                                        \
    __syncthreads();                                                         \
    {                                                                        \
        float a = sb3[o32];                                                  \
        _Pragma("unroll 8")                                                  \
        for (int f = 0; f < OHH; f++)                                        \
            a = fmaf(sW3[f * 32 + o32], sh2[f * R4 + rw], a);                \
        kb[o32 * R4 + rw] = a;                                               \
    }                                                                        \
    __syncthreads();

    for (int s = 0; s < NSTEP; s++) {
        ODE_EVAL(zc)
        za[tid]  = fmaf(hs / 6.f, kb[tid], zc[tid]);
        zin[tid] = fmaf(hs * 0.5f, kb[tid], zc[tid]);
        __syncthreads();
        ODE_EVAL(zin)
        za[tid]  = fmaf(hs / 3.f, kb[tid], za[tid]);
        zin[tid] = fmaf(hs * 0.5f, kb[tid], zc[tid]);
        __syncthreads();
        ODE_EVAL(zin)
        za[tid]  = fmaf(hs / 3.f, kb[tid], za[tid]);
        zin[tid] = fmaf(hs, kb[tid], zc[tid]);
        __syncthreads();
        ODE_EVAL(zin)
        zc[tid] = fmaf(hs / 6.f, kb[tid], za[tid]);
        __syncthreads();
    }
#undef ODE_EVAL

    {
        float a0 = __ldg(db1 + o64), a1 = a0;
        #pragma unroll 8
        for (int f = 0; f < LL; f++) {
            float wv = __ldg(dW1 + o64 * LL + f);
            float4 zv = *(const float4*)(zc + f * R4);
            float u0 = rp ? zv.y : zv.x;
            float u1 = rp ? zv.w : zv.z;
            a0 = fmaf(wv, u0, a0); a1 = fmaf(wv, u1, a1);
        }
        float w2 = __ldg(dW2 + o64);
        sh1[o64 * R4 + rp]     = fmaxf(a0, 0.f) * w2;
        sh1[o64 * R4 + rp + 2] = fmaxf(a1, 0.f) * w2;
    }
    __syncthreads();
    {
        const int row = tid >> 5, l = tid & 31;
        float s = sh1[l * R4 + row] + sh1[(l + 32) * R4 + row];
        #pragma unroll
        for (int off = 16; off; off >>= 1) s += __shfl_down_sync(0xffffffffu, s, off);
        if (l == 0) out[row0 + row] = s + __ldg(db2);
    }
}

__global__ void __launch_bounds__(1024) kl_kernel(float* __restrict__ out)
{
    __shared__ float s[1024];
    const int t = threadIdx.x;
    s[t] = g_klrow[t] + g_klrow[t + 1024];
    __syncthreads();
    for (int o = 512; o; o >>= 1) {
        if (t < o) s[t] += s[t + o];
        __syncthreads();
    }
    if (t == 0) out[BB] = -0.5f * s[0] / ((float)BB * (float)LL);
}

// =====================================================================
extern "C" void kernel_launch(void* const* d_in, const int* in_sizes, int n_in,
                              void* d_out, int out_size)
{
    const float* values = (const float*)d_in[1];
    const float* maskp  = (const float*)d_in[2];
    const int*   seql   = (const int*)d_in[3];
    const float* eps    = (const float*)d_in[4];
    const float* W_ih   = (const float*)d_in[5];
    const float* W_hh   = (const float*)d_in[6];
    const float* b_ih   = (const float*)d_in[7];
    const float* b_hh   = (const float*)d_in[8];
    const float* W_z0   = (const float*)d_in[9];
    const float* b_z0   = (const float*)d_in[10];
    const float* oW1    = (const float*)d_in[11];
    const float* ob1    = (const float*)d_in[12];
    const float* oW2    = (const float*)d_in[13];
    const float* ob2    = (const float*)d_in[14];
    const float* oW3    = (const float*)d_in[15];
    const float* ob3    = (const float*)d_in[16];
    const float* dW1    = (const float*)d_in[17];
    const float* db1    = (const float*)d_in[18];
    const float* dW2    = (const float*)d_in[19];
    const float* db2    = (const float*)d_in[20];
    float* out = (float*)d_out;

    cudaFuncSetAttribute(gru_kernel, cudaFuncAttributeMaxDynamicSharedMemorySize, GRU_SMEM_B);

    xp_kernel<<<dim3(16, 64), 256>>>(values, maskp, W_ih, b_ih, seql);
    gru_kernel<<<256, 128, GRU_SMEM_B>>>(seql, W_hh, b_hh);
    tail_kernel<<<512, 128>>>(eps, W_z0, b_z0, oW1, ob1, oW2, ob2, oW3, ob3,
                              dW1, db1, dW2, db2, out);
    kl_kernel<<<1, 1024>>>(out);
}

// round 16
// speedup vs baseline: 1.1697x; 1.0044x over previous
#include <cuda_runtime.h>
#include <cuda_fp16.h>
#include <cstdint>

#define BB 2048
#define TT 256
#define NVV 32
#define HH 64
#define GG 192
#define LL 32
#define OHH 64

__device__ float g_h[BB * HH];
__device__ float g_klrow[BB];
// xp planes: [t][bpair(1024)][g(192)] as half2 (pair = 2 batch rows). 201 MB.
__device__ __half2 g_xp2[(size_t)TT * 1024 * GG];

__device__ __forceinline__ float tanh_hw(float x) {
    float y;
    asm("tanh.approx.f32 %0, %1;" : "=f"(y) : "f"(x));
    return y;
}
__device__ __forceinline__ float sig_hw(float x) {
    return fmaf(tanh_hw(0.5f * x), 0.5f, 0.5f);
}

// =====================================================================
// xp GEMM via fp16 tensor cores, fp32 accumulate. (unchanged)
// =====================================================================
__global__ void __launch_bounds__(256) xp_kernel(
    const float* __restrict__ values, const float* __restrict__ maskp,
    const float* __restrict__ W_ih, const float* __restrict__ b_ih,
    const int* __restrict__ seqlen)
{
    __shared__ __half sW[192 * 72];
    __shared__ __half sX[128 * 72];

    const int tid = threadIdx.x;
    const int bbase = blockIdx.x * 128;
    const int sqmax = __ldg(seqlen + bbase);   // sorted desc -> max of block

    if (sqmax <= (int)(blockIdx.y * 4)) return;

    for (int i = tid; i < GG * HH; i += 256) {
        int g = i >> 6, f = i & 63;
        sW[g * 72 + f] = __float2half(W_ih[i]);
    }

    const int w = tid >> 5, l = tid & 31;
    const int wg = w >> 2;
    const int wb = w & 3;
    const int l4 = l >> 2;
    const int l2 = (l & 3) * 2;

    for (int tloc = 0; tloc < 4; tloc++) {
        const int t = blockIdx.y * 4 + tloc;
        if (t >= sqmax) break;
        const int tt = TT - 1 - t;

        if (tloc > 0) __syncthreads();
        for (int i = tid; i < 128 * HH; i += 256) {
            int bl = i >> 6, f = i & 63;
            size_t base = (size_t)(bbase + bl) * TT * NVV + (size_t)tt * NVV;
            float v = (f < NVV) ? values[base + f] : maskp[base + f - NVV];
            sX[bl * 72 + f] = __float2half(v);
        }
        __syncthreads();

        #pragma unroll
        for (int gt = 0; gt < 6; gt++) {
            const int g0 = wg * 96 + gt * 16;
            uint32_t a[4][4];
            #pragma unroll
            for (int kk = 0; kk < 4; kk++) {
                const __half* p = &sW[(g0 + l4) * 72 + kk * 16 + l2];
                a[kk][0] = *(const uint32_t*)(p);
                a[kk][1] = *(const uint32_t*)(p + 8 * 72);
                a[kk][2] = *(const uint32_t*)(p + 8);
                a[kk][3] = *(const uint32_t*)(p + 8 * 72 + 8);
            }
            const float bias0 = __ldg(b_ih + g0 + l4);
            const float bias1 = __ldg(b_ih + g0 + 8 + l4);

            #pragma unroll
            for (int bt = 0; bt < 4; bt++) {
                const int b0 = wb * 32 + bt * 8;
                float c0 = bias0, c1 = bias0, c2 = bias1, c3 = bias1;
                #pragma unroll
                for (int kk = 0; kk < 4; kk++) {
                    const __half* bp = &sX[(b0 + l4) * 72 + kk * 16 + l2];
                    uint32_t br0 = *(const uint32_t*)(bp);
                    uint32_t br1 = *(const uint32_t*)(bp + 8);
                    asm volatile(
                        "mma.sync.aligned.m16n8k16.row.col.f32.f16.f16.f32 "
                        "{%0,%1,%2,%3}, {%4,%5,%6,%7}, {%8,%9}, {%0,%1,%2,%3};\n"
                        : "+f"(c0), "+f"(c1), "+f"(c2), "+f"(c3)
                        : "r"(a[kk][0]), "r"(a[kk][1]), "r"(a[kk][2]), "r"(a[kk][3]),
                          "r"(br0), "r"(br1));
                }
                const int gg = g0 + l4;
                const int bpair = (bbase + b0 + l2) >> 1;
                size_t base = ((size_t)t * 1024 + bpair) * 192 + gg;
                g_xp2[base]     = __floats2half2_rn(c0, c1);
                g_xp2[base + 8] = __floats2half2_rn(c2, c3);
            }
        }
    }
}

// =====================================================================
// GRU scan: pure-fp16-W MMA, 12 MMA/warp/step, DEPTH-1 chains:
// 4 independent partial accumulators per gate (one per kt tile).
// 256 CTAs x 128 thr, 8 rows/CTA; early exit + complementary pairing.
// =====================================================================
#define GRU_SMEM_B ((192*72 + 2*8*72) * 2)

__global__ void __launch_bounds__(128) gru_kernel(
    const int* __restrict__ seqlen,
    const float* __restrict__ W_hh, const float* __restrict__ b_hh)
{
    extern __shared__ char smem[];
    __half* sWhi = (__half*)smem;            // [192][72]
    __half* sH   = sWhi + 192 * 72;          // [2buf][8][72]
#define SH(buf, n, k) sH[(((buf) * 8) + (n)) * 72 + (k)]

    const int tid  = threadIdx.x;
    const int bid  = blockIdx.x;
    const int job  = (bid < 148) ? bid : (403 - bid);
    const int row0 = job * 8;
    const int seqmax = __ldg(seqlen + row0);

    for (int i = tid; i < GG * HH; i += 128) {
        int g = i >> 6, k = i & 63;
        sWhi[g * 72 + k] = __float2half(W_hh[i]);
    }
    for (int i = tid; i < 2 * 8 * 72; i += 128) sH[i] = __float2half(0.f);
    __syncthreads();

    const int l  = tid & 31;
    const int mw = tid >> 5;       // 0..3: j-tile 16mw..+15
    const int r  = l >> 2;         // 0..7
    const int cq = (l & 3) * 2;    // 0,2,4,6

    uint32_t Ahi[3][4][4];
    #pragma unroll
    for (int mt = 0; mt < 3; mt++) {
        const int g0 = 16 * mw + 64 * mt;
        #pragma unroll
        for (int kt = 0; kt < 4; kt++) {
            const int k0 = kt * 16 + cq;
            Ahi[mt][kt][0] = *(const uint32_t*)&sWhi[(g0 + r) * 72 + k0];
            Ahi[mt][kt][1] = *(const uint32_t*)&sWhi[(g0 + r + 8) * 72 + k0];
            Ahi[mt][kt][2] = *(const uint32_t*)&sWhi[(g0 + r) * 72 + k0 + 8];
            Ahi[mt][kt][3] = *(const uint32_t*)&sWhi[(g0 + r + 8) * 72 + k0 + 8];
        }
    }

    const int j0 = 16 * mw + r;
    const int j1 = j0 + 8;
    const int nloc = cq;
    const int grow = row0 + nloc;
    const float bhr0 = __ldg(b_hh + j0),        bhr1 = __ldg(b_hh + j1);
    const float bhz0 = __ldg(b_hh + 64 + j0),   bhz1 = __ldg(b_hh + 64 + j1);
    const float bhn0 = __ldg(b_hh + 128 + j0),  bhn1 = __ldg(b_hh + 128 + j1);
    const int seq0 = __ldg(seqlen + grow);
    const int seq1 = __ldg(seqlen + grow + 1);

    float hp[4] = {0.f, 0.f, 0.f, 0.f};

    const size_t bp = (size_t)(grow >> 1);
    const __half2* __restrict__ xplane = g_xp2 + bp * 192;
#define XPLANE(T) (xplane + (size_t)(T) * 1024 * 192)

    __half2 cur0 = XPLANE(0)[j0],       cur1 = XPLANE(0)[j1];
    __half2 cur2 = XPLANE(0)[64 + j0],  cur3 = XPLANE(0)[64 + j1];
    __half2 cur4 = XPLANE(0)[128 + j0], cur5 = XPLANE(0)[128 + j1];
    __half2 nxt0 = XPLANE(1)[j0],       nxt1 = XPLANE(1)[j1];
    __half2 nxt2 = XPLANE(1)[64 + j0],  nxt3 = XPLANE(1)[64 + j1];
    __half2 nxt4 = XPLANE(1)[128 + j0], nxt5 = XPLANE(1)[128 + j1];

    for (int t = 0; t < seqmax; t++) {
        const int buf = t & 1;
        __half2 tm0, tm1, tm2, tm3, tm4, tm5;
        if (t + 2 < TT) {
            const __half2* pl = XPLANE(t + 2);
            tm0 = pl[j0];       tm1 = pl[j1];
            tm2 = pl[64 + j0];  tm3 = pl[64 + j1];
            tm4 = pl[128 + j0]; tm5 = pl[128 + j1];
        }

        uint32_t bhi[4][2];
        #pragma unroll
        for (int kt = 0; kt < 4; kt++) {
            const int k0 = kt * 16 + cq;
            bhi[kt][0] = *(const uint32_t*)&SH(buf, r, k0);
            bhi[kt][1] = *(const uint32_t*)&SH(buf, r, k0 + 8);
        }

        float2 fR0 = __half22float2(cur0), fR1 = __half22float2(cur1);
        float2 fZ0 = __half22float2(cur2), fZ1 = __half22float2(cur3);
        float2 fN0 = __half22float2(cur4), fN1 = __half22float2(cur5);
        // 4 independent partial accumulators per gate (one per kt) -> depth-1 chains
        float p[3][4][4];
        #pragma unroll
        for (int mt = 0; mt < 3; mt++)
            #pragma unroll
            for (int q = 1; q < 4; q++)
                #pragma unroll
                for (int e = 0; e < 4; e++) p[mt][q][e] = 0.f;
        p[0][0][0] = fR0.x + bhr0; p[0][0][1] = fR0.y + bhr0;
        p[0][0][2] = fR1.x + bhr1; p[0][0][3] = fR1.y + bhr1;
        p[1][0][0] = fZ0.x + bhz0; p[1][0][1] = fZ0.y + bhz0;
        p[1][0][2] = fZ1.x + bhz1; p[1][0][3] = fZ1.y + bhz1;
        p[2][0][0] = bhn0; p[2][0][1] = bhn0;
        p[2][0][2] = bhn1; p[2][0][3] = bhn1;
        float fxn[4] = {fN0.x, fN0.y, fN1.x, fN1.y};

#define MMA_ACC(P, A, B0, B1)                                                \
        asm volatile(                                                        \
            "mma.sync.aligned.m16n8k16.row.col.f32.f16.f16.f32 "             \
            "{%0,%1,%2,%3}, {%4,%5,%6,%7}, {%8,%9}, {%0,%1,%2,%3};\n"        \
            : "+f"((P)[0]), "+f"((P)[1]), "+f"((P)[2]), "+f"((P)[3])         \
            : "r"((A)[0]), "r"((A)[1]), "r"((A)[2]), "r"((A)[3]),            \
              "r"(B0), "r"(B1));

        // 12 fully independent MMAs (no accumulator reuse within the step)
        #pragma unroll
        for (int kt = 0; kt < 4; kt++) {
            MMA_ACC(p[0][kt], Ahi[0][kt], bhi[kt][0], bhi[kt][1])
            MMA_ACC(p[1][kt], Ahi[1][kt], bhi[kt][0], bhi[kt][1])
            MMA_ACC(p[2][kt], Ahi[2][kt], bhi[kt][0], bhi[kt][1])
        }
#undef MMA_ACC

        #pragma unroll
        for (int e = 0; e < 4; e++) {
            float aR = (p[0][0][e] + p[0][1][e]) + (p[0][2][e] + p[0][3][e]);
            float aZ = (p[1][0][e] + p[1][1][e]) + (p[1][2][e] + p[1][3][e]);
            float aN = (p[2][0][e] + p[2][1][e]) + (p[2][2][e] + p[2][3][e]);
            float rr = sig_hw(aR);
            float zz = sig_hw(aZ);
            float nn = tanh_hw(fxn[e] + rr * aN);
            float hn = (1.f - zz) * nn + zz * hp[e];
            int sq = (e & 1) ? seq1 : seq0;
            hp[e] = (t < sq) ? hn : hp[e];
        }

        const int b2 = buf ^ 1;
        #pragma unroll
        for (int e = 0; e < 4; e++) {
            const int nn_ = nloc + (e & 1);
            const int jj_ = (e < 2) ? j0 : j1;
            SH(b2, nn_, jj_) = __float2half(hp[e]);
        }

        cur0 = nxt0; cur1 = nxt1; cur2 = nxt2; cur3 = nxt3; cur4 = nxt4; cur5 = nxt5;
        nxt0 = tm0; nxt1 = tm1; nxt2 = tm2; nxt3 = tm3; nxt4 = tm4; nxt5 = tm5;
        __syncthreads();
    }

    g_h[(size_t)(grow)     * HH + j0] = hp[0];
    g_h[(size_t)(grow + 1) * HH + j0] = hp[1];
    g_h[(size_t)(grow)     * HH + j1] = hp[2];
    g_h[(size_t)(grow + 1) * HH + j1] = hp[3];
#undef SH
#undef XPLANE
}

// =====================================================================
// Fused tail: z0 -> RK4 ODE (NSTEP=4) -> decoder -> KL partials.
// =====================================================================
#define NSTEP 4
#define R4 4

__global__ void __launch_bounds__(128) tail_kernel(
    const float* __restrict__ eps,
    const float* __restrict__ Wz0, const float* __restrict__ bz0,
    const float* __restrict__ W1, const float* __restrict__ b1,
    const float* __restrict__ W2, const float* __restrict__ b2,
    const float* __restrict__ W3, const float* __restrict__ b3,
    const float* __restrict__ dW1, const float* __restrict__ db1,
    const float* __restrict__ dW2, const float* __restrict__ db2,
    float* __restrict__ out)
{
    __shared__ float sW1[32 * 64];
    __shared__ float sW2[64 * 64];
    __shared__ float sW3[64 * 32];
    __shared__ float sb1[64], sb2[64], sb3[32];
    __shared__ float sH[R4 * 64];
    __shared__ float z0p[R4 * 64];
    __shared__ float zc[32 * R4], za[32 * R4], zin[32 * R4], kb[32 * R4];
    __shared__ float sh1[64 * R4], sh2[64 * R4];

    const int tid = threadIdx.x;
    const int row0 = blockIdx.x * R4;

    for (int i = tid; i < OHH * LL; i += 128) {
        int o = i >> 5, f = i & 31;
        sW1[f * 64 + o] = W1[i];
    }
    for (int i = tid; i < LL * OHH; i += 128) {
        int l = i >> 6, f2 = i & 63;
        sW3[f2 * 32 + l] = W3[i];
    }
    for (int i = tid; i < OHH * OHH; i += 128) {
        int o = i >> 6, f = i & 63;
        sW2[f * 64 + o] = W2[i];
    }
    if (tid < 64) { sb1[tid] = b1[tid]; sb2[tid] = b2[tid]; }
    if (tid < 32) sb3[tid] = b3[tid];
    for (int i = tid; i < R4 * 64; i += 128)
        sH[i] = g_h[(size_t)(row0 + (i >> 6)) * HH + (i & 63)];
    __syncthreads();

    {
        const int o = tid & 63, rp = tid >> 6;
        float m0 = __ldg(bz0 + o), m1 = m0;
        #pragma unroll 8
        for (int f = 0; f < HH; f++) {
            float wv = __ldg(Wz0 + o * HH + f);
            m0 = fmaf(wv, sH[rp * 64 + f], m0);
            m1 = fmaf(wv, sH[(rp + 2) * 64 + f], m1);
        }
        z0p[rp * 64 + o] = m0;
        z0p[(rp + 2) * 64 + o] = m1;
    }
    __syncthreads();

    {
        const int row = tid >> 5, l = tid & 31;
        float m  = z0p[row * 64 + l];
        float lv = z0p[row * 64 + 32 + l];
        float z = m + eps[(size_t)(row0 + row) * LL + l] * __expf(0.5f * lv);
        zc[l * R4 + row] = z;
        float kt = 1.f + lv - m * m - __expf(lv);
        #pragma unroll
        for (int off = 16; off; off >>= 1) kt += __shfl_down_sync(0xffffffffu, kt, off);
        if (l == 0) g_klrow[row0 + row] = kt;
    }
    __syncthreads();

    const float hs = 48.0f / NSTEP;
    const int o64 = tid & 63, rp = tid >> 6;
    const int o32 = tid & 31, rw = tid >> 5;

#define ODE_EVAL(SRC)                                                        \
    {                                                                        \
        float a0 = sb1[o64], a1 = a0;                                        \
        _Pragma("unroll 8")                                                  \
        for (int f = 0; f < LL; f++) {                                       \
            float wv = sW1[f * 64 + o64];                                    \
            float4 zv = *(const float4*)((SRC) + f * R4);                    \
            float u0 = rp ? zv.y : zv.x;                                     \
            float u1 = rp ? zv.w : zv.z;                                     \
            a0 = fmaf(wv, u0, a0); a1 = fmaf(wv, u1, a1);                    \
        }                                                                    \
        sh1[o64 * R4 + rp]     = tanh_hw(a0);                                \
        sh1[o64 * R4 + rp + 2] = tanh_hw(a1);                                \
    }                                                                        \
    __syncthreads();                                                         \
    {                                                                        \
        float a0 = sb2[o64], a1 = a0;                                        \
        _Pragma("unroll 8")                                                  \
        for (int f = 0; f < OHH; f++) {                                      \
            float wv = sW2[f * 64 + o64];                                    \
            float4 zv = *(const float4*)(sh1 + f * R4);                      \
            float u0 = rp ? zv.y : zv.x;                                     \
            float u1 = rp ? zv.w : zv.z;                                     \
            a0 = fmaf(wv, u0, a0); a1 = fmaf(wv, u1, a1);                    \
        }                                                                    \
        sh2[o64 * R4 + rp]     = tanh_hw(a0);                                \
        sh2[o64 * R4 + rp + 2] = tanh_hw(a1);                                \
    }                                                                        \
    __syncthreads();                                                         \
    {                                                                        \
        float a = sb3[o32];                                                  \
        _Pragma("unroll 8")                                                  \
        for (int f = 0; f < OHH; f++)                                        \
            a = fmaf(sW3[f * 32 + o32], sh2[f * R4 + rw], a);                \
        kb[o32 * R4 + rw] = a;                                               \
    }                                                                        \
    __syncthreads();

    for (int s = 0; s < NSTEP; s++) {
        ODE_EVAL(zc)
        za[tid]  = fmaf(hs / 6.f, kb[tid], zc[tid]);
        zin[tid] = fmaf(hs * 0.5f, kb[tid], zc[tid]);
        __syncthreads();
        ODE_EVAL(zin)
        za[tid]  = fmaf(hs / 3.f, kb[tid], za[tid]);
        zin[tid] = fmaf(hs * 0.5f, kb[tid], zc[tid]);
        __syncthreads();
        ODE_EVAL(zin)
        za[tid]  = fmaf(hs / 3.f, kb[tid], za[tid]);
        zin[tid] = fmaf(hs, kb[tid], zc[tid]);
        __syncthreads();
        ODE_EVAL(zin)
        zc[tid] = fmaf(hs / 6.f, kb[tid], za[tid]);
        __syncthreads();
    }
#undef ODE_EVAL

    {
        float a0 = __ldg(db1 + o64), a1 = a0;
        #pragma unroll 8
        for (int f = 0; f < LL; f++) {
            float wv = __ldg(dW1 + o64 * LL + f);
            float4 zv = *(const float4*)(zc + f * R4);
            float u0 = rp ? zv.y : zv.x;
            float u1 = rp ? zv.w : zv.z;
            a0 = fmaf(wv, u0, a0); a1 = fmaf(wv, u1, a1);
        }
        float w2 = __ldg(dW2 + o64);
        sh1[o64 * R4 + rp]     = fmaxf(a0, 0.f) * w2;
        sh1[o64 * R4 + rp + 2] = fmaxf(a1, 0.f) * w2;
    }
    __syncthreads();
    {
        const int row = tid >> 5, l = tid & 31;
        float s = sh1[l * R4 + row] + sh1[(l + 32) * R4 + row];
        #pragma unroll
        for (int off = 16; off; off >>= 1) s += __shfl_down_sync(0xffffffffu, s, off);
        if (l == 0) out[row0 + row] = s + __ldg(db2);
    }
}

__global__ void __launch_bounds__(1024) kl_kernel(float* __restrict__ out)
{
    __shared__ float s[1024];
    const int t = threadIdx.x;
    s[t] = g_klrow[t] + g_klrow[t + 1024];
    __syncthreads();
    for (int o = 512; o; o >>= 1) {
        if (t < o) s[t] += s[t + o];
        __syncthreads();
    }
    if (t == 0) out[BB] = -0.5f * s[0] / ((float)BB * (float)LL);
}

// =====================================================================
extern "C" void kernel_launch(void* const* d_in, const int* in_sizes, int n_in,
                              void* d_out, int out_size)
{
    const float* values = (const float*)d_in[1];
    const float* maskp  = (const float*)d_in[2];
    const int*   seql   = (const int*)d_in[3];
    const float* eps    = (const float*)d_in[4];
    const float* W_ih   = (const float*)d_in[5];
    const float* W_hh   = (const float*)d_in[6];
    const float* b_ih   = (const float*)d_in[7];
    const float* b_hh   = (const float*)d_in[8];
    const float* W_z0   = (const float*)d_in[9];
    const float* b_z0   = (const float*)d_in[10];
    const float* oW1    = (const float*)d_in[11];
    const float* ob1    = (const float*)d_in[12];
    const float* oW2    = (const float*)d_in[13];
    const float* ob2    = (const float*)d_in[14];
    const float* oW3    = (const float*)d_in[15];
    const float* ob3    = (const float*)d_in[16];
    const float* dW1    = (const float*)d_in[17];
    const float* db1    = (const float*)d_in[18];
    const float* dW2    = (const float*)d_in[19];
    const float* db2    = (const float*)d_in[20];
    float* out = (float*)d_out;

    cudaFuncSetAttribute(gru_kernel, cudaFuncAttributeMaxDynamicSharedMemorySize, GRU_SMEM_B);

    xp_kernel<<<dim3(16, 64), 256>>>(values, maskp, W_ih, b_ih, seql);
    gru_kernel<<<256, 128, GRU_SMEM_B>>>(seql, W_hh, b_hh);
    tail_kernel<<<512, 128>>>(eps, W_z0, b_z0, oW1, ob1, oW2, ob2, oW3, ob3,
                              dW1, db1, dW2, db2, out);
    kl_kernel<<<1, 1024>>>(out);
}